// round 1
// baseline (speedup 1.0000x reference)
#include <cuda_runtime.h>
#include <math.h>

// Problem constants: B=4, H=16 -> BH=64; S=1024; D=64; max_rel_pos=32 (33 causal buckets)
#define BH    64
#define SEQ   1024
#define DH    64
#define BQ    32          // query rows per CTA
#define NTHR  512         // 16 warps
#define TK    128         // k/v tile rows
#define NJ    33          // relative-position buckets used under causal mask (dist in [-32,0])

// shared memory layout (floats)
#define OFF_KT   0        // K transposed [64][129] (union: V [128][64] = 8192)
#define OFF_Q    8256     // Q rows [32][64]
#define OFF_QPE  10304    // qpe [32][34]
#define OFF_PEK  11392    // pe_k rows 0..32, [33][66]
#define OFF_PEV  13570    // pe_v rows 0..32, [33][66]
#define OFF_P    15748    // p rows [32][1024]
#define SM_FLOATS 48516   // total = 194,064 bytes

__device__ __forceinline__ float wmax(float v) {
    #pragma unroll
    for (int o = 16; o > 0; o >>= 1) v = fmaxf(v, __shfl_xor_sync(0xffffffffu, v, o));
    return v;
}
__device__ __forceinline__ float wsum(float v) {
    #pragma unroll
    for (int o = 16; o > 0; o >>= 1) v += __shfl_xor_sync(0xffffffffu, v, o);
    return v;
}

__global__ __launch_bounds__(NTHR, 1)
void relattn_kernel(const float* __restrict__ Q, const float* __restrict__ K,
                    const float* __restrict__ V, const float* __restrict__ PEK,
                    const float* __restrict__ PEV,
                    float* __restrict__ Out, float* __restrict__ Pout)
{
    extern __shared__ float sm[];
    float* smKT  = sm + OFF_KT;   // K^T: [d][k] stride 129 (conflict-free column reads)
    float* smV   = sm + OFF_KT;   // union with smKT: V row-major [128][64]
    float* smQ   = sm + OFF_Q;
    float* smQPE = sm + OFF_QPE;
    float* smPEK = sm + OFF_PEK;
    float* smPEV = sm + OFF_PEV;
    float* smP   = sm + OFF_P;

    const int bh   = blockIdx.y;
    const int qblk = blockIdx.x;
    const int q0   = qblk * BQ;
    const int tid  = threadIdx.x;
    const int warp = tid >> 5;
    const int lane = tid & 31;

    const float* Qb = Q + (size_t)bh * SEQ * DH;
    const float* Kb = K + (size_t)bh * SEQ * DH;
    const float* Vb = V + (size_t)bh * SEQ * DH;

    // ---- stage Q rows + pe tables ----
    for (int i = tid; i < BQ * DH / 4; i += NTHR)
        ((float4*)smQ)[i] = ((const float4*)(Qb + (size_t)q0 * DH))[i];
    for (int i = tid; i < NJ * DH / 4; i += NTHR) {
        int r = i >> 4, c = (i & 15) * 4;
        float4 a = *(const float4*)(PEK + r * DH + c);
        smPEK[r * 66 + c + 0] = a.x; smPEK[r * 66 + c + 1] = a.y;
        smPEK[r * 66 + c + 2] = a.z; smPEK[r * 66 + c + 3] = a.w;
        float4 b = *(const float4*)(PEV + r * DH + c);
        smPEV[r * 66 + c + 0] = b.x; smPEV[r * 66 + c + 1] = b.y;
        smPEV[r * 66 + c + 2] = b.z; smPEV[r * 66 + c + 3] = b.w;
    }
    __syncthreads();

    // ---- qpe[r][j] = q_r . pe_k[j]  (j = 0..32) ----
    for (int idx = tid; idx < BQ * NJ; idx += NTHR) {
        int r = idx / NJ, j = idx - r * NJ;
        const float* qr = smQ + r * DH;
        const float* pr = smPEK + j * 66;
        float acc = 0.f;
        #pragma unroll
        for (int d = 0; d < DH; d++) acc = fmaf(qr[d], pr[d], acc);
        smQPE[r * 34 + j] = acc;
    }
    __syncthreads();

    // ---- per-warp rows ----
    const int r0 = warp * 2;
    const int qr0 = q0 + r0, qr1 = qr0 + 1;
    const int qe = q0 + BQ - 1;
    const int ntiles = qe / TK + 1;   // uniform per CTA

    float s0[32], s1[32];
    #pragma unroll
    for (int i = 0; i < 32; i++) { s0[i] = 0.f; s1[i] = 0.f; }

    // ---- score pass: S = Q K^T + bias ----
    #pragma unroll
    for (int kt = 0; kt < 8; kt++) {
        if (kt < ntiles) {
            // load K tile transposed into smKT[d*129 + kk]
            for (int i = tid; i < TK * DH / 4; i += NTHR) {
                int kk = i >> 4, c = (i & 15) * 4;
                float4 v = *(const float4*)(Kb + ((size_t)(kt * TK + kk)) * DH + c);
                smKT[(c + 0) * 129 + kk] = v.x;
                smKT[(c + 1) * 129 + kk] = v.y;
                smKT[(c + 2) * 129 + kk] = v.z;
                smKT[(c + 3) * 129 + kk] = v.w;
            }
            __syncthreads();

            const float* q0p = smQ + r0 * DH;
            const float* q1p = q0p + DH;
            #pragma unroll
            for (int d = 0; d < DH; d += 4) {
                float4 qa4 = *(const float4*)(q0p + d);
                float4 qb4 = *(const float4*)(q1p + d);
                float qa[4] = {qa4.x, qa4.y, qa4.z, qa4.w};
                float qb[4] = {qb4.x, qb4.y, qb4.z, qb4.w};
                #pragma unroll
                for (int dd = 0; dd < 4; dd++) {
                    const float* kr = smKT + (d + dd) * 129 + lane;
                    float k0 = kr[0], k1 = kr[32], k2 = kr[64], k3 = kr[96];
                    s0[kt*4+0] = fmaf(qa[dd], k0, s0[kt*4+0]);
                    s0[kt*4+1] = fmaf(qa[dd], k1, s0[kt*4+1]);
                    s0[kt*4+2] = fmaf(qa[dd], k2, s0[kt*4+2]);
                    s0[kt*4+3] = fmaf(qa[dd], k3, s0[kt*4+3]);
                    s1[kt*4+0] = fmaf(qb[dd], k0, s1[kt*4+0]);
                    s1[kt*4+1] = fmaf(qb[dd], k1, s1[kt*4+1]);
                    s1[kt*4+2] = fmaf(qb[dd], k2, s1[kt*4+2]);
                    s1[kt*4+3] = fmaf(qb[dd], k3, s1[kt*4+3]);
                }
            }
            // relative-position bias
            #pragma unroll
            for (int ii = 0; ii < 4; ii++) {
                int k = kt * TK + ii * 32 + lane;
                int j0 = min(max(k - qr0 + 32, 0), 32);
                int j1 = min(max(k - qr1 + 32, 0), 32);
                s0[kt*4+ii] += smQPE[r0 * 34 + j0];
                s1[kt*4+ii] += smQPE[(r0 + 1) * 34 + j1];
            }
            __syncthreads();
        }
    }

    // ---- causal mask + exact softmax (scale folded into exp) ----
    const float NEG = -1e30f;
    float m0 = NEG, m1 = NEG;
    #pragma unroll
    for (int i = 0; i < 32; i++) {
        int k = i * 32 + lane;
        if (k > qr0) s0[i] = NEG;
        if (k > qr1) s1[i] = NEG;
        m0 = fmaxf(m0, s0[i]); m1 = fmaxf(m1, s1[i]);
    }
    m0 = wmax(m0); m1 = wmax(m1);
    const float isd = 0.125f;  // 1/sqrt(64)
    float l0 = 0.f, l1 = 0.f;
    #pragma unroll
    for (int i = 0; i < 32; i++) {
        s0[i] = __expf((s0[i] - m0) * isd);
        s1[i] = __expf((s1[i] - m1) * isd);
        l0 += s0[i]; l1 += s1[i];
    }
    l0 = wsum(l0); l1 = wsum(l1);
    const float il0 = 1.f / l0, il1 = 1.f / l1;

    // normalize, store p rows to smem; accumulate far-bucket mass w0 (frees s regs)
    float w00 = 0.f, w01 = 0.f;
    #pragma unroll
    for (int i = 0; i < 32; i++) {
        int k = i * 32 + lane;
        float p0 = s0[i] * il0;
        float p1 = s1[i] * il1;
        smP[r0 * SEQ + k]       = p0;
        smP[(r0 + 1) * SEQ + k] = p1;
        if (k <= qr0 - 32) w00 += p0;
        if (k <= qr1 - 32) w01 += p1;
    }
    w00 = wsum(w00); w01 = wsum(w01);
    __syncthreads();   // smP complete; smKT free for V tiles

    // ---- V pass: out = P V ----
    float o00 = 0.f, o01 = 0.f, o10 = 0.f, o11 = 0.f;  // 2 rows x float2(d=2*lane,2*lane+1)
    #pragma unroll
    for (int vt = 0; vt < 8; vt++) {
        if (vt < ntiles) {
            for (int i = tid; i < TK * DH / 4; i += NTHR)
                ((float4*)smV)[i] = ((const float4*)(Vb + (size_t)vt * TK * DH))[i];
            __syncthreads();
            const float* p0r = smP + r0 * SEQ + vt * TK;
            const float* p1r = p0r + SEQ;
            #pragma unroll 4
            for (int kk = 0; kk < TK; kk++) {
                float2 v2 = *(const float2*)(smV + kk * DH + 2 * lane);
                float p0 = p0r[kk], p1 = p1r[kk];
                o00 = fmaf(p0, v2.x, o00); o01 = fmaf(p0, v2.y, o01);
                o10 = fmaf(p1, v2.x, o10); o11 = fmaf(p1, v2.y, o11);
            }
            __syncthreads();
        }
    }

    // ---- relative-position value epilogue: out += sum_j w[j] * pe_v[j] ----
    #pragma unroll
    for (int j = 0; j <= 32; j++) {
        float wa, wb;
        if (j == 0) { wa = w00; wb = w01; }
        else {
            int ka = qr0 - 32 + j, kb = qr1 - 32 + j;
            wa = (ka >= 0) ? smP[r0 * SEQ + ka] : 0.f;
            wb = (kb >= 0) ? smP[(r0 + 1) * SEQ + kb] : 0.f;
        }
        float2 pv = *(const float2*)(smPEV + j * 66 + 2 * lane);
        o00 = fmaf(wa, pv.x, o00); o01 = fmaf(wa, pv.y, o01);
        o10 = fmaf(wb, pv.x, o10); o11 = fmaf(wb, pv.y, o11);
    }

    // ---- write output ----
    float2 w0v = make_float2(o00, o01);
    float2 w1v = make_float2(o10, o11);
    *(float2*)(Out + ((size_t)bh * SEQ + qr0) * DH + 2 * lane) = w0v;
    *(float2*)(Out + ((size_t)bh * SEQ + qr1) * DH + 2 * lane) = w1v;

    // ---- write p_attn rows (coalesced float4 from smem) ----
    float4* pg = (float4*)(Pout + (size_t)bh * SEQ * SEQ + (size_t)q0 * SEQ);
    const float4* ps = (const float4*)smP;
    for (int i = tid; i < BQ * SEQ / 4; i += NTHR)
        pg[i] = ps[i];
}

extern "C" void kernel_launch(void* const* d_in, const int* in_sizes, int n_in,
                              void* d_out, int out_size)
{
    (void)in_sizes; (void)n_in; (void)out_size;
    const float* Q   = (const float*)d_in[0];
    const float* K   = (const float*)d_in[1];
    const float* V   = (const float*)d_in[2];
    const float* PEK = (const float*)d_in[3];
    const float* PEV = (const float*)d_in[4];
    float* Out  = (float*)d_out;                       // [4,16,1024,64]
    float* Pout = Out + (size_t)BH * SEQ * DH;         // [4,16,1024,1024] follows

    size_t smem = (size_t)SM_FLOATS * sizeof(float);   // 194,064 B
    cudaFuncSetAttribute(relattn_kernel,
                         cudaFuncAttributeMaxDynamicSharedMemorySize, (int)smem);
    dim3 grid(SEQ / BQ, BH);   // (32, 64)
    relattn_kernel<<<grid, NTHR, smem>>>(Q, K, V, PEK, PEV, Out, Pout);
}

// round 3
// speedup vs baseline: 2.5506x; 2.5506x over previous
#include <cuda_runtime.h>
#include <math.h>
#include <stdint.h>

// B=4,H=16 -> BH=64; S=1024; D=64; rel-pos P=32
#define BH   64
#define SEQ  1024
#define DH   64
#define NTHR 256
#define ISD  0.125f
#define NEGINF (-INFINITY)

// smem layout (bytes)
#define KS_STRIDE 68
#define VS_STRIDE 72
#define PS_STRIDE 132
#define OFF_KS   0                          // K tile [128][68] tf32 bits   34816
#define OFF_VS   34816                      // V tile [128][72] tf32 bits   36864
#define OFF_PS   71680                      // P tile [128][132] (also Q staging) 67584
#define OFF_QPE  139264                     // qpe [128][34] f32            17408
#define OFF_W    156672                     // taps [128][34] f32           17408
#define OFF_PEK  174080                     // pe_k [33][66] f32             8712
#define OFF_PEV  182792                     //                               8712
#define OFF_MR   191504                     // m partials [128][2]           1024
#define OFF_LR   192528                     // l partials [128][2]           1024
#define OFF_WR   193552                     // w0 partials [128][2]          1024
#define SMEM_TOTAL 194576

static __device__ __forceinline__ uint32_t f2tf(float x) {
    uint32_t r; asm("cvt.rna.tf32.f32 %0, %1;" : "=r"(r) : "f"(x)); return r;
}
static __device__ __forceinline__ void mma8(float* d, const uint32_t* a,
                                            uint32_t b0, uint32_t b1) {
    asm volatile("mma.sync.aligned.m16n8k8.row.col.f32.tf32.tf32.f32 "
        "{%0,%1,%2,%3},{%4,%5,%6,%7},{%8,%9},{%0,%1,%2,%3};"
        : "+f"(d[0]), "+f"(d[1]), "+f"(d[2]), "+f"(d[3])
        : "r"(a[0]), "r"(a[1]), "r"(a[2]), "r"(a[3]), "r"(b0), "r"(b1));
}

__global__ __launch_bounds__(NTHR, 1)
void relattn_mma(const float* __restrict__ Q, const float* __restrict__ K,
                 const float* __restrict__ V, const float* __restrict__ PEK,
                 const float* __restrict__ PEV,
                 float* __restrict__ Out, float* __restrict__ Pout)
{
    extern __shared__ char sm8[];
    uint32_t* ksu = (uint32_t*)(sm8 + OFF_KS);
    uint32_t* vsu = (uint32_t*)(sm8 + OFF_VS);
    float*    sPS = (float*)(sm8 + OFF_PS);
    uint32_t* psu = (uint32_t*)(sm8 + OFF_PS);
    float*    sQPE= (float*)(sm8 + OFF_QPE);
    float*    sW  = (float*)(sm8 + OFF_W);
    float*    sPEK= (float*)(sm8 + OFF_PEK);
    float*    sPEV= (float*)(sm8 + OFF_PEV);
    float*    sMR = (float*)(sm8 + OFF_MR);
    float*    sLR = (float*)(sm8 + OFF_LR);
    float*    sWR = (float*)(sm8 + OFF_WR);

    const int tid = threadIdx.x, lane = tid & 31, warp = tid >> 5;
    const int g = lane >> 2, tg = lane & 3;
    const int wm = warp & 3, wn = warp >> 2;
    const int rm = wm * 32, cn = wn * 64, dn = wn * 32;

    // longest CTAs first (qblk descending)
    const int bx = blockIdx.x;
    const int qblk = 7 - (bx >> 6);
    const int bh = bx & 63;
    const int q0 = qblk * 128;
    const int ntiles = qblk + 1;

    const float* Qb = Q + (size_t)bh * SEQ * DH;
    const float* Kb = K + (size_t)bh * SEQ * DH;
    const float* Vb = V + (size_t)bh * SEQ * DH;

    // ---- stage Q (raw fp32) into sPS; pe tables; zero taps ----
    for (int i = tid; i < 128 * 16; i += NTHR) {
        int r = i >> 4, c = (i & 15) * 4;
        *(float4*)(sPS + r * PS_STRIDE + c) =
            *(const float4*)(Qb + (size_t)(q0 + r) * DH + c);
    }
    for (int i = tid; i < 33 * 16; i += NTHR) {
        int r = i >> 4, c = (i & 15) * 4;
        float4 a = *(const float4*)(PEK + r * DH + c);
        sPEK[r*66+c] = a.x; sPEK[r*66+c+1] = a.y; sPEK[r*66+c+2] = a.z; sPEK[r*66+c+3] = a.w;
        float4 b = *(const float4*)(PEV + r * DH + c);
        sPEV[r*66+c] = b.x; sPEV[r*66+c+1] = b.y; sPEV[r*66+c+2] = b.z; sPEV[r*66+c+3] = b.w;
    }
    for (int i = tid; i < 128 * 34; i += NTHR) sW[i] = 0.f;
    __syncthreads();

    // ---- qpe[row][j] = q_row . pe_k[j]  (fp32) ----
    {
        int row = tid >> 1, half = tid & 1;
        float qreg[64];
        #pragma unroll
        for (int d = 0; d < 64; d++) qreg[d] = sPS[row * PS_STRIDE + d];
        int j0 = half * 16, jn = half ? 17 : 16;
        #pragma unroll 1
        for (int jj = 0; jj < jn; jj++) {
            int j = j0 + jj;
            float a = 0.f;
            #pragma unroll
            for (int d = 0; d < 64; d++) a = fmaf(qreg[d], sPEK[j*66+d], a);
            sQPE[row * 34 + j] = a;
        }
    }

    // ---- Q A-fragments, resident (tf32 rna) ----
    uint32_t qa[2][8][4];
    #pragma unroll
    for (int mt = 0; mt < 2; mt++)
        #pragma unroll
        for (int ks = 0; ks < 8; ks++) {
            int r = rm + 16*mt + g, c = 8*ks + tg;
            qa[mt][ks][0] = f2tf(sPS[r*PS_STRIDE + c]);
            qa[mt][ks][1] = f2tf(sPS[(r+8)*PS_STRIDE + c]);
            qa[mt][ks][2] = f2tf(sPS[r*PS_STRIDE + c + 4]);
            qa[mt][ks][3] = f2tf(sPS[(r+8)*PS_STRIDE + c + 4]);
        }

    // ================= phase 1: softmax stats =================
    float m_run[4] = {NEGINF, NEGINF, NEGINF, NEGINF};
    float l_run[4] = {0.f, 0.f, 0.f, 0.f};

    for (int kt = 0; kt < ntiles; kt++) {
        const float* Kt = Kb + (size_t)kt * 128 * DH;
        __syncthreads();
        for (int i = tid; i < 128 * 16; i += NTHR) {
            int r = i >> 4, c = (i & 15) * 4;
            float4 v = *(const float4*)(Kt + (size_t)r * DH + c);
            uint4 u; u.x = f2tf(v.x); u.y = f2tf(v.y); u.z = f2tf(v.z); u.w = f2tf(v.w);
            *(uint4*)(ksu + r * KS_STRIDE + c) = u;
        }
        __syncthreads();

        float acc[2][8][4] = {};
        #pragma unroll
        for (int nt = 0; nt < 8; nt++)
            #pragma unroll
            for (int ks = 0; ks < 8; ks++) {
                int base = (cn + 8*nt + g) * KS_STRIDE + 8*ks + tg;
                uint32_t b0 = ksu[base], b1 = ksu[base + 4];
                mma8(acc[0][nt], qa[0][ks], b0, b1);
                mma8(acc[1][nt], qa[1][ks], b0, b1);
            }

        // bias + mask + per-tile row max
        float mloc[4] = {NEGINF, NEGINF, NEGINF, NEGINF};
        #pragma unroll
        for (int mt = 0; mt < 2; mt++)
            #pragma unroll
            for (int nt = 0; nt < 8; nt++)
                #pragma unroll
                for (int c = 0; c < 4; c++) {
                    int s = mt*2 + (c>>1);
                    int row = rm + 16*mt + 8*(c>>1) + g;
                    int col = kt*128 + cn + 8*nt + 2*tg + (c&1);
                    int qg = q0 + row;
                    float v = NEGINF;
                    if (col <= qg) {
                        int j = col - qg + 32; j = j < 0 ? 0 : j;
                        v = acc[mt][nt][c] + sQPE[row*34 + j];
                    }
                    acc[mt][nt][c] = v;
                    mloc[s] = fmaxf(mloc[s], v);
                }
        #pragma unroll
        for (int s = 0; s < 4; s++) {
            mloc[s] = fmaxf(mloc[s], __shfl_xor_sync(0xffffffffu, mloc[s], 1));
            mloc[s] = fmaxf(mloc[s], __shfl_xor_sync(0xffffffffu, mloc[s], 2));
        }
        if (tg == 0)
            #pragma unroll
            for (int s = 0; s < 4; s++) {
                int row = rm + 16*(s>>1) + 8*(s&1) + g;
                sMR[row*2 + wn] = mloc[s];
            }
        __syncthreads();
        float mtile[4];
        #pragma unroll
        for (int s = 0; s < 4; s++) {
            int row = rm + 16*(s>>1) + 8*(s&1) + g;
            mtile[s] = fmaxf(sMR[row*2], sMR[row*2+1]);
        }
        float lloc[4] = {0.f, 0.f, 0.f, 0.f};
        #pragma unroll
        for (int mt = 0; mt < 2; mt++)
            #pragma unroll
            for (int nt = 0; nt < 8; nt++)
                #pragma unroll
                for (int c = 0; c < 4; c++) {
                    int s = mt*2 + (c>>1);
                    lloc[s] += __expf((acc[mt][nt][c] - mtile[s]) * ISD);
                }
        #pragma unroll
        for (int s = 0; s < 4; s++) {
            lloc[s] += __shfl_xor_sync(0xffffffffu, lloc[s], 1);
            lloc[s] += __shfl_xor_sync(0xffffffffu, lloc[s], 2);
        }
        if (tg == 0)
            #pragma unroll
            for (int s = 0; s < 4; s++) {
                int row = rm + 16*(s>>1) + 8*(s&1) + g;
                sLR[row*2 + wn] = lloc[s];
            }
        __syncthreads();
        #pragma unroll
        for (int s = 0; s < 4; s++) {
            int row = rm + 16*(s>>1) + 8*(s&1) + g;
            float lt = sLR[row*2] + sLR[row*2+1];
            float mn = fmaxf(m_run[s], mtile[s]);
            l_run[s] = l_run[s] * __expf((m_run[s] - mn) * ISD)
                     + lt       * __expf((mtile[s] - mn) * ISD);
            m_run[s] = mn;
        }
    }

    // ================= phase 2: recompute, emit p, PV =================
    float m_f[4], invl[4];
    #pragma unroll
    for (int s = 0; s < 4; s++) { m_f[s] = m_run[s]; invl[s] = 1.f / l_run[s]; }
    float o[2][4][4] = {};
    float w0[4] = {0.f, 0.f, 0.f, 0.f};

    for (int kt = 0; kt < ntiles; kt++) {
        const float* Kt = Kb + (size_t)kt * 128 * DH;
        const float* Vt = Vb + (size_t)kt * 128 * DH;
        __syncthreads();
        for (int i = tid; i < 128 * 16; i += NTHR) {
            int r = i >> 4, c = (i & 15) * 4;
            float4 v = *(const float4*)(Kt + (size_t)r * DH + c);
            uint4 u; u.x = f2tf(v.x); u.y = f2tf(v.y); u.z = f2tf(v.z); u.w = f2tf(v.w);
            *(uint4*)(ksu + r * KS_STRIDE + c) = u;
            float4 w = *(const float4*)(Vt + (size_t)r * DH + c);
            uint4 uw; uw.x = f2tf(w.x); uw.y = f2tf(w.y); uw.z = f2tf(w.z); uw.w = f2tf(w.w);
            *(uint4*)(vsu + r * VS_STRIDE + c) = uw;
        }
        __syncthreads();

        float acc[2][8][4] = {};
        #pragma unroll
        for (int nt = 0; nt < 8; nt++)
            #pragma unroll
            for (int ks = 0; ks < 8; ks++) {
                int base = (cn + 8*nt + g) * KS_STRIDE + 8*ks + tg;
                uint32_t b0 = ksu[base], b1 = ksu[base + 4];
                mma8(acc[0][nt], qa[0][ks], b0, b1);
                mma8(acc[1][nt], qa[1][ks], b0, b1);
            }

        #pragma unroll
        for (int mt = 0; mt < 2; mt++)
            #pragma unroll
            for (int nt = 0; nt < 8; nt++) {
                float p[4];
                #pragma unroll
                for (int c = 0; c < 4; c++) {
                    int s = mt*2 + (c>>1);
                    int row = rm + 16*mt + 8*(c>>1) + g;
                    int col = kt*128 + cn + 8*nt + 2*tg + (c&1);
                    int qg = q0 + row;
                    float v = NEGINF;
                    if (col <= qg) {
                        int j = col - qg + 32; j = j < 0 ? 0 : j;
                        v = acc[mt][nt][c] + sQPE[row*34 + j];
                    }
                    float pe = __expf((v - m_f[s]) * ISD) * invl[s];
                    p[c] = pe;
                    if (col <= qg - 32) w0[s] += pe;
                    else if (col <= qg) sW[row*34 + (col - qg + 32)] = pe;
                }
                int rowL = rm + 16*mt + g, rowH = rowL + 8;
                int colb = kt*128 + cn + 8*nt + 2*tg;
                *(float2*)(Pout + ((size_t)bh*SEQ + q0 + rowL)*SEQ + colb) = make_float2(p[0], p[1]);
                *(float2*)(Pout + ((size_t)bh*SEQ + q0 + rowH)*SEQ + colb) = make_float2(p[2], p[3]);
                int kloc = cn + 8*nt + 2*tg;
                uint2 u01; u01.x = f2tf(p[0]); u01.y = f2tf(p[1]);
                uint2 u23; u23.x = f2tf(p[2]); u23.y = f2tf(p[3]);
                *(uint2*)(psu + rowL*PS_STRIDE + kloc) = u01;
                *(uint2*)(psu + rowH*PS_STRIDE + kloc) = u23;
            }
        __syncthreads();

        // PV: O[rm..rm+31][dn..dn+31] += P_tile x V_tile
        #pragma unroll 2
        for (int ks = 0; ks < 16; ks++) {
            uint32_t pa[2][4];
            #pragma unroll
            for (int mt = 0; mt < 2; mt++) {
                int r = rm + 16*mt + g, c = 8*ks + tg;
                pa[mt][0] = psu[r*PS_STRIDE + c];
                pa[mt][1] = psu[(r+8)*PS_STRIDE + c];
                pa[mt][2] = psu[r*PS_STRIDE + c + 4];
                pa[mt][3] = psu[(r+8)*PS_STRIDE + c + 4];
            }
            #pragma unroll
            for (int nt = 0; nt < 4; nt++) {
                uint32_t b0 = vsu[(8*ks + tg) * VS_STRIDE + dn + 8*nt + g];
                uint32_t b1 = vsu[(8*ks + tg + 4) * VS_STRIDE + dn + 8*nt + g];
                mma8(o[0][nt], pa[0], b0, b1);
                mma8(o[1][nt], pa[1], b0, b1);
            }
        }
    }
    __syncthreads();

    // ---- w0 reduce (quad + cross-warp) ----
    #pragma unroll
    for (int s = 0; s < 4; s++) {
        w0[s] += __shfl_xor_sync(0xffffffffu, w0[s], 1);
        w0[s] += __shfl_xor_sync(0xffffffffu, w0[s], 2);
    }
    if (tg == 0)
        #pragma unroll
        for (int s = 0; s < 4; s++) {
            int row = rm + 16*(s>>1) + 8*(s&1) + g;
            sWR[row*2 + wn] = w0[s];
        }
    __syncthreads();
    float w0f[4];
    #pragma unroll
    for (int s = 0; s < 4; s++) {
        int row = rm + 16*(s>>1) + 8*(s&1) + g;
        w0f[s] = sWR[row*2] + sWR[row*2+1];
    }

    // ---- rel-pos value epilogue: o += sum_j w_j * pe_v[j] ----
    #pragma unroll 1
    for (int j = 0; j <= 32; j++) {
        float wj[4];
        #pragma unroll
        for (int s = 0; s < 4; s++) {
            int row = rm + 16*(s>>1) + 8*(s&1) + g;
            wj[s] = (j == 0) ? w0f[s] : sW[row*34 + j];
        }
        #pragma unroll
        for (int nt = 0; nt < 4; nt++) {
            float pe0 = sPEV[j*66 + dn + 8*nt + 2*tg];
            float pe1 = sPEV[j*66 + dn + 8*nt + 2*tg + 1];
            #pragma unroll
            for (int mt = 0; mt < 2; mt++) {
                o[mt][nt][0] = fmaf(wj[mt*2+0], pe0, o[mt][nt][0]);
                o[mt][nt][1] = fmaf(wj[mt*2+0], pe1, o[mt][nt][1]);
                o[mt][nt][2] = fmaf(wj[mt*2+1], pe0, o[mt][nt][2]);
                o[mt][nt][3] = fmaf(wj[mt*2+1], pe1, o[mt][nt][3]);
            }
        }
    }

    // ---- write output ----
    #pragma unroll
    for (int mt = 0; mt < 2; mt++)
        #pragma unroll
        for (int nt = 0; nt < 4; nt++) {
            int rowL = rm + 16*mt + g, rowH = rowL + 8;
            int colb = dn + 8*nt + 2*tg;
            *(float2*)(Out + ((size_t)bh*SEQ + q0 + rowL)*DH + colb) = make_float2(o[mt][nt][0], o[mt][nt][1]);
            *(float2*)(Out + ((size_t)bh*SEQ + q0 + rowH)*DH + colb) = make_float2(o[mt][nt][2], o[mt][nt][3]);
        }

    // ---- zero-fill masked p region ----
    int zc = SEQ - ntiles * 128;
    if (zc > 0) {
        int zq = zc >> 2;
        float4 z = make_float4(0.f, 0.f, 0.f, 0.f);
        float* base = Pout + ((size_t)bh*SEQ + q0)*SEQ + ntiles*128;
        for (int i = tid; i < 128 * zq; i += NTHR) {
            int r = i / zq, c = (i - r * zq) * 4;
            *(float4*)(base + (size_t)r * SEQ + c) = z;
        }
    }
}

extern "C" void kernel_launch(void* const* d_in, const int* in_sizes, int n_in,
                              void* d_out, int out_size)
{
    (void)in_sizes; (void)n_in; (void)out_size;
    const float* Q   = (const float*)d_in[0];
    const float* K   = (const float*)d_in[1];
    const float* V   = (const float*)d_in[2];
    const float* PEK = (const float*)d_in[3];
    const float* PEV = (const float*)d_in[4];
    float* Out  = (float*)d_out;
    float* Pout = Out + (size_t)BH * SEQ * DH;

    cudaFuncSetAttribute(relattn_mma, cudaFuncAttributeMaxDynamicSharedMemorySize, SMEM_TOTAL);
    relattn_mma<<<512, NTHR, SMEM_TOTAL>>>(Q, K, V, PEK, PEV, Out, Pout);
}